// round 13
// baseline (speedup 1.0000x reference)
#include <cuda_runtime.h>
#include <cuda_fp16.h>
#include <cuda_fp8.h>

#define NN 100000
#define NE 3200000
#define HID 16

typedef unsigned int u32;
typedef unsigned short u16;

// ---------------- scratch ----------------
__device__ uint4  g_e8[NE];           // 51.2 MB edge features (fp8 e4m3, 16B/edge)
__device__ __align__(32) __half g_agg_s[NN][HID];   // 3.2 MB f16 accumulators
__device__ __align__(32) __half g_agg_r[NN][HID];   // 3.2 MB
__device__ __half g_nodes_h[NN];      // 200 KB -- fits in one SM's L1D
__device__ float  g_part[1024];
__device__ float  g_norm;
__device__ float  g_inv_norm;

// ---------------- helpers ----------------
__device__ __forceinline__ u32 h2u(__half2 h) { return *(u32*)&h; }
__device__ __forceinline__ __half2 u2h(u32 v) { return *(__half2*)&v; }
__device__ __forceinline__ u32 packh2(float a, float b) {
    return h2u(__floats2half2_rn(a, b));
}
__device__ __forceinline__ float2 unpackh2(u32 v) {
    return __half22float2(u2h(v));
}
__device__ __forceinline__ float hsum2(__half2 a) {
    float2 f = __half22float2(a);
    return f.x + f.y;
}
__device__ __forceinline__ void red_add_v4h(void* p, u32 a, u32 b, u32 c, u32 d) {
    asm volatile("red.global.add.noftz.v4.f16x2 [%0], {%1, %2, %3, %4};"
                 :: "l"(p), "r"(a), "r"(b), "r"(c), "r"(d) : "memory");
}
__device__ __forceinline__ u16 pack8(float a, float b) {
    float2 f = make_float2(a, b);
    return (u16)__nv_cvt_float2_to_fp8x2(f, __NV_SATFINITE, __NV_E4M3);
}
__device__ __forceinline__ __half2 unp8(u16 v) {
    __half2_raw hr = __nv_cvt_fp8x2_to_halfraw2((__nv_fp8x2_storage_t)v, __NV_E4M3);
    return *(__half2*)&hr;
}

// 16->16 layer in f16x2 (weights as 2 uint4 of half2 k-pairs)
__device__ __forceinline__ __half2 dot16h(const uint4 wa, const uint4 wb,
                                          const __half2* x, __half2 acc) {
    acc = __hfma2(u2h(wa.x), x[0], acc);
    acc = __hfma2(u2h(wa.y), x[1], acc);
    acc = __hfma2(u2h(wa.z), x[2], acc);
    acc = __hfma2(u2h(wa.w), x[3], acc);
    acc = __hfma2(u2h(wb.x), x[4], acc);
    acc = __hfma2(u2h(wb.y), x[5], acc);
    acc = __hfma2(u2h(wb.z), x[6], acc);
    acc = __hfma2(u2h(wb.w), x[7], acc);
    return acc;
}

// ---------------- launch 0: zero aggs + per-block max |x| ----------------
__global__ __launch_bounds__(256) void k_norm_part(const float* __restrict__ x) {
    __shared__ float sm[8];
    int gid = blockIdx.x * blockDim.x + threadIdx.x;
    const int nf4 = NN * HID * 2 / 16;
    uint4 z = make_uint4(0u, 0u, 0u, 0u);
    if (gid < nf4) {
        ((uint4*)g_agg_s)[gid] = z;
        ((uint4*)g_agg_r)[gid] = z;
    }
    float m = 0.f;
    const float4* x4 = (const float4*)x;
    const int n4 = NE / 4;
    for (int i = gid; i < n4; i += gridDim.x * blockDim.x) {
        float4 v = x4[i];
        m = fmaxf(m, fmaxf(fmaxf(fabsf(v.x), fabsf(v.y)), fmaxf(fabsf(v.z), fabsf(v.w))));
    }
#pragma unroll
    for (int o = 16; o; o >>= 1) m = fmaxf(m, __shfl_xor_sync(0xffffffffu, m, o));
    if ((threadIdx.x & 31) == 0) sm[threadIdx.x >> 5] = m;
    __syncthreads();
    if (threadIdx.x < 8) {
        m = sm[threadIdx.x];
#pragma unroll
        for (int o = 4; o; o >>= 1) m = fmaxf(m, __shfl_xor_sync(0xffu, m, o));
        if (threadIdx.x == 0) g_part[blockIdx.x] = m;
    }
}

// ---------------- launch 1: finalize norm ----------------
__global__ __launch_bounds__(1024) void k_norm_final() {
    __shared__ float sm[32];
    float m = g_part[threadIdx.x];
#pragma unroll
    for (int o = 16; o; o >>= 1) m = fmaxf(m, __shfl_xor_sync(0xffffffffu, m, o));
    if ((threadIdx.x & 31) == 0) sm[threadIdx.x >> 5] = m;
    __syncthreads();
    if (threadIdx.x < 32) {
        m = sm[threadIdx.x];
#pragma unroll
        for (int o = 16; o; o >>= 1) m = fmaxf(m, __shfl_xor_sync(0xffffffffu, m, o));
        if (threadIdx.x == 0) { g_norm = m; g_inv_norm = 1.0f / m; }
    }
}

// ---------------- launch 2: encoder (2 edges/thread) ----------------
__global__ __launch_bounds__(256) void k_enc(
    const float* __restrict__ edges_init,
    const int* __restrict__ senders, const int* __restrict__ receivers,
    const float* __restrict__ w1g, const float* __restrict__ b1g,
    const float* __restrict__ w2g, const float* __restrict__ b2g)
{
    __shared__ __align__(16) float w1[HID], b1[HID];
    __shared__ __align__(16) u32 w2h[HID * 8];
    __shared__ __align__(16) u32 b2h[HID];
    int t = threadIdx.x;
    if (t < HID) {
        w1[t] = w1g[t]; b1[t] = b1g[t];
        b2h[t] = packh2(b2g[t], 0.f);
    }
    if (t < 128) {
        int j = t >> 3, kk = t & 7;
        w2h[j * 8 + kk] = packh2(w2g[j * HID + 2 * kk], w2g[j * HID + 2 * kk + 1]);
    }
    __syncthreads();

    int p = blockIdx.x * blockDim.x + t;
    if (p >= NE / 2) return;
    int i0 = 2 * p;

    float2 xi = ((const float2*)edges_init)[p];
    float inv = g_inv_norm;
    float x[2] = {xi.x * inv, xi.y * inv};
    int2 s2 = ((const int2*)senders)[p];
    int2 r2 = ((const int2*)receivers)[p];

    const uint4* w2v = (const uint4*)w2h;
    u32 uu[2][8];
    uint4 st[2];

#pragma unroll
    for (int ed = 0; ed < 2; ed++) {
        float h[HID];
#pragma unroll
        for (int j = 0; j < HID; j++) h[j] = fmaxf(fmaf(w1[j], x[ed], b1[j]), 0.f);
        __half2 hp[8];
#pragma unroll
        for (int q = 0; q < 8; q++) hp[q] = __floats2half2_rn(h[2 * q], h[2 * q + 1]);

        float e[HID];
#pragma unroll
        for (int j = 0; j < HID; j++) {
            __half2 acc = dot16h(w2v[j * 2], w2v[j * 2 + 1], hp, u2h(b2h[j]));
            e[j] = hsum2(acc);
        }
        u16 p8[8];
#pragma unroll
        for (int q = 0; q < 8; q++) {
            uu[ed][q] = packh2(e[2 * q], e[2 * q + 1]);
            p8[q] = pack8(e[2 * q], e[2 * q + 1]);
        }
        st[ed] = make_uint4((u32)p8[0] | ((u32)p8[1] << 16),
                            (u32)p8[2] | ((u32)p8[3] << 16),
                            (u32)p8[4] | ((u32)p8[5] << 16),
                            (u32)p8[6] | ((u32)p8[7] << 16));
    }
    g_e8[i0] = st[0];
    g_e8[i0 + 1] = st[1];

    char* ps0 = (char*)g_agg_s + (size_t)s2.x * 32;
    char* pr0 = (char*)g_agg_r + (size_t)r2.x * 32;
    char* ps1 = (char*)g_agg_s + (size_t)s2.y * 32;
    char* pr1 = (char*)g_agg_r + (size_t)r2.y * 32;
    red_add_v4h(ps0,      uu[0][0], uu[0][1], uu[0][2], uu[0][3]);
    red_add_v4h(ps1,      uu[1][0], uu[1][1], uu[1][2], uu[1][3]);
    red_add_v4h(pr0,      uu[0][0], uu[0][1], uu[0][2], uu[0][3]);
    red_add_v4h(pr1,      uu[1][0], uu[1][1], uu[1][2], uu[1][3]);
    red_add_v4h(ps0 + 16, uu[0][4], uu[0][5], uu[0][6], uu[0][7]);
    red_add_v4h(ps1 + 16, uu[1][4], uu[1][5], uu[1][6], uu[1][7]);
    red_add_v4h(pr0 + 16, uu[0][4], uu[0][5], uu[0][6], uu[0][7]);
    red_add_v4h(pr1 + 16, uu[1][4], uu[1][5], uu[1][6], uu[1][7]);
}

// ---------------- node update: fp32 math, f16 node store ----------------
template <bool FIRST>
__global__ __launch_bounds__(256) void k_node(
    const float* __restrict__ in_nodes,
    const float* __restrict__ w1g, const float* __restrict__ b1g,
    const float* __restrict__ w2g, const float* __restrict__ b2g)
{
    __shared__ __align__(16) float w1[HID * 36], b1[HID], w2[HID];
    __shared__ float b2s;
    int t = threadIdx.x;
    for (int i = t; i < HID * 33; i += blockDim.x) {
        int j = i / 33, c = i % 33;
        w1[j * 36 + c] = w1g[i];
    }
    if (t < HID) { b1[t] = b1g[t]; w2[t] = w2g[t]; }
    if (t == 0) b2s = b2g[0];
    __syncthreads();

    int n = blockIdx.x * blockDim.x + t;
    if (n >= NN) return;

    float xin[33];
    xin[0] = FIRST ? in_nodes[n] : __half2float(g_nodes_h[n]);
    uint4* as4 = (uint4*)g_agg_s[n];
    uint4* ar4 = (uint4*)g_agg_r[n];
#pragma unroll
    for (int half = 0; half < 2; half++) {
        uint4 a = as4[half];
        u32 w[4] = {a.x, a.y, a.z, a.w};
#pragma unroll
        for (int q = 0; q < 4; q++) {
            float2 f = unpackh2(w[q]);
            xin[1 + half * 8 + 2 * q] = f.x;
            xin[2 + half * 8 + 2 * q] = f.y;
        }
        uint4 b = ar4[half];
        u32 v[4] = {b.x, b.y, b.z, b.w};
#pragma unroll
        for (int q = 0; q < 4; q++) {
            float2 f = unpackh2(v[q]);
            xin[17 + half * 8 + 2 * q] = f.x;
            xin[18 + half * 8 + 2 * q] = f.y;
        }
    }
    uint4 z = make_uint4(0u, 0u, 0u, 0u);
    as4[0] = z; as4[1] = z; ar4[0] = z; ar4[1] = z;

    const float4* w1v = (const float4*)w1;
    float out = b2s;
#pragma unroll
    for (int j = 0; j < HID; j++) {
        float hj = b1[j];
#pragma unroll
        for (int q = 0; q < 8; q++) {
            float4 w = w1v[j * 9 + q];
            hj = fmaf(w.x, xin[4 * q], hj);
            hj = fmaf(w.y, xin[4 * q + 1], hj);
            hj = fmaf(w.z, xin[4 * q + 2], hj);
            hj = fmaf(w.w, xin[4 * q + 3], hj);
        }
        hj = fmaf(w1v[j * 9 + 8].x, xin[32], hj);
        out = fmaf(w2[j], fmaxf(hj, 0.f), out);
    }
    g_nodes_h[n] = __float2half_rn(out);
}

// ---------------- edge update: f16x2 MLPs, fp8 e, f16 node gathers ----------------
template <bool LAST>
__global__ __launch_bounds__(256) void k_edge(
    const int* __restrict__ senders, const int* __restrict__ receivers,
    const float* __restrict__ ew1g, const float* __restrict__ eb1g,
    const float* __restrict__ ew2g, const float* __restrict__ eb2g,
    const float* __restrict__ dw1g, const float* __restrict__ db1g,
    const float* __restrict__ dw2g, const float* __restrict__ db2g,
    const float* __restrict__ edges_init, const float* __restrict__ alpha_p,
    float* __restrict__ out)
{
    __shared__ __align__(16) u32 ew1h[HID * 8];
    __shared__ __align__(16) u32 ew1n[HID];
    __shared__ __align__(16) u32 eb1h[HID];
    __shared__ __align__(16) u32 ew2h[HID * 8];
    __shared__ __align__(16) u32 eb2h[HID];
    __shared__ __align__(16) u32 dw1h[HID * 8];
    __shared__ __align__(16) u32 db1h[HID];
    __shared__ __align__(16) u32 dw2h[8];
    __shared__ float db2s, alphas;
    int t = threadIdx.x;
    if (t < 128) {
        int j = t >> 3, kk = t & 7;
        ew1h[j * 8 + kk] = packh2(ew1g[j * 18 + 2 * kk], ew1g[j * 18 + 2 * kk + 1]);
        ew2h[j * 8 + kk] = packh2(ew2g[j * HID + 2 * kk], ew2g[j * HID + 2 * kk + 1]);
    }
    if (t < HID) {
        ew1n[t] = packh2(ew1g[t * 18 + 16], ew1g[t * 18 + 17]);
        eb1h[t] = packh2(eb1g[t], 0.f);
        eb2h[t] = packh2(eb2g[t], 0.f);
    }
    if (LAST) {
        if (t >= 128 && t < 256) {
            int tt = t - 128;
            int j = tt >> 3, kk = tt & 7;
            dw1h[j * 8 + kk] = packh2(dw1g[j * HID + 2 * kk], dw1g[j * HID + 2 * kk + 1]);
        }
        if (t >= 16 && t < 32) db1h[t - 16] = packh2(db1g[t - 16], 0.f);
        if (t >= 32 && t < 40) dw2h[t - 32] = packh2(dw2g[2 * (t - 32)], dw2g[2 * (t - 32) + 1]);
        if (t == 40) { db2s = db2g[0]; alphas = alpha_p[0]; }
    }
    __syncthreads();

    int p = blockIdx.x * blockDim.x + t;
    if (p >= NE / 2) return;
    int i0 = 2 * p;

    int2 s2 = ((const int2*)senders)[p];
    int2 r2 = ((const int2*)receivers)[p];
    __half ns0 = g_nodes_h[s2.x], nr0 = g_nodes_h[r2.x];
    __half ns1 = g_nodes_h[s2.y], nr1 = g_nodes_h[r2.y];
    uint4 ev0 = g_e8[i0];
    uint4 ev1 = g_e8[i0 + 1];

    const uint4* w1v = (const uint4*)ew1h;
    const uint4* w2v = (const uint4*)ew2h;

    float e2a[2][HID];
#pragma unroll
    for (int ed = 0; ed < 2; ed++) {
        uint4 ev = ed ? ev1 : ev0;
        __half2 epair[8];
        epair[0] = unp8((u16)(ev.x & 0xffffu)); epair[1] = unp8((u16)(ev.x >> 16));
        epair[2] = unp8((u16)(ev.y & 0xffffu)); epair[3] = unp8((u16)(ev.y >> 16));
        epair[4] = unp8((u16)(ev.z & 0xffffu)); epair[5] = unp8((u16)(ev.z >> 16));
        epair[6] = unp8((u16)(ev.w & 0xffffu)); epair[7] = unp8((u16)(ev.w >> 16));
        __half2 npair = ed ? __halves2half2(ns1, nr1) : __halves2half2(ns0, nr0);

        float h[HID];
#pragma unroll
        for (int j = 0; j < HID; j++) {
            __half2 acc = dot16h(w1v[j * 2], w1v[j * 2 + 1], epair, u2h(eb1h[j]));
            acc = __hfma2(u2h(ew1n[j]), npair, acc);
            h[j] = fmaxf(hsum2(acc), 0.f);
        }
        __half2 hp[8];
#pragma unroll
        for (int q = 0; q < 8; q++) hp[q] = __floats2half2_rn(h[2 * q], h[2 * q + 1]);
#pragma unroll
        for (int j = 0; j < HID; j++) {
            __half2 acc = dot16h(w2v[j * 2], w2v[j * 2 + 1], hp, u2h(eb2h[j]));
            e2a[ed][j] = hsum2(acc);
        }
    }

    if (!LAST) {
        u32 uu[2][8];
        uint4 st[2];
#pragma unroll
        for (int ed = 0; ed < 2; ed++) {
            u16 p8[8];
#pragma unroll
            for (int q = 0; q < 8; q++) {
                uu[ed][q] = packh2(e2a[ed][2 * q], e2a[ed][2 * q + 1]);
                p8[q] = pack8(e2a[ed][2 * q], e2a[ed][2 * q + 1]);
            }
            st[ed] = make_uint4((u32)p8[0] | ((u32)p8[1] << 16),
                                (u32)p8[2] | ((u32)p8[3] << 16),
                                (u32)p8[4] | ((u32)p8[5] << 16),
                                (u32)p8[6] | ((u32)p8[7] << 16));
        }
        g_e8[i0] = st[0];
        g_e8[i0 + 1] = st[1];

        char* ps0 = (char*)g_agg_s + (size_t)s2.x * 32;
        char* pr0 = (char*)g_agg_r + (size_t)r2.x * 32;
        char* ps1 = (char*)g_agg_s + (size_t)s2.y * 32;
        char* pr1 = (char*)g_agg_r + (size_t)r2.y * 32;
        red_add_v4h(ps0,      uu[0][0], uu[0][1], uu[0][2], uu[0][3]);
        red_add_v4h(ps1,      uu[1][0], uu[1][1], uu[1][2], uu[1][3]);
        red_add_v4h(pr0,      uu[0][0], uu[0][1], uu[0][2], uu[0][3]);
        red_add_v4h(pr1,      uu[1][0], uu[1][1], uu[1][2], uu[1][3]);
        red_add_v4h(ps0 + 16, uu[0][4], uu[0][5], uu[0][6], uu[0][7]);
        red_add_v4h(ps1 + 16, uu[1][4], uu[1][5], uu[1][6], uu[1][7]);
        red_add_v4h(pr0 + 16, uu[0][4], uu[0][5], uu[0][6], uu[0][7]);
        red_add_v4h(pr1 + 16, uu[1][4], uu[1][5], uu[1][6], uu[1][7]);
    } else {
        const uint4* dv = (const uint4*)dw1h;
        float2 ei = ((const float2*)edges_init)[p];
        float scale = alphas * g_norm;
        float oo[2];
#pragma unroll
        for (int ed = 0; ed < 2; ed++) {
            __half2 e2p[8];
#pragma unroll
            for (int q = 0; q < 8; q++)
                e2p[q] = __floats2half2_rn(e2a[ed][2 * q], e2a[ed][2 * q + 1]);
            float h2[HID];
#pragma unroll
            for (int j = 0; j < HID; j++) {
                __half2 acc = dot16h(dv[j * 2], dv[j * 2 + 1], e2p, u2h(db1h[j]));
                h2[j] = fmaxf(hsum2(acc), 0.f);
            }
            __half2 h2p[8];
#pragma unroll
            for (int q = 0; q < 8; q++) h2p[q] = __floats2half2_rn(h2[2 * q], h2[2 * q + 1]);
            __half2 acc = __floats2half2_rn(0.f, 0.f);
#pragma unroll
            for (int q = 0; q < 8; q++) acc = __hfma2(u2h(dw2h[q]), h2p[q], acc);
            float sdec = db2s + hsum2(acc);
            oo[ed] = fmaf(scale, sdec, ed ? ei.y : ei.x);
        }
        ((float2*)out)[p] = make_float2(oo[0], oo[1]);
    }
}

// ---------------- launch ----------------
extern "C" void kernel_launch(void* const* d_in, const int* in_sizes, int n_in,
                              void* d_out, int out_size)
{
    const float* nodes      = (const float*)d_in[0];
    const float* edges_init = (const float*)d_in[1];
    const int*   senders    = (const int*)d_in[2];
    const int*   receivers  = (const int*)d_in[3];
    const float* enc_w1 = (const float*)d_in[4];
    const float* enc_b1 = (const float*)d_in[5];
    const float* enc_w2 = (const float*)d_in[6];
    const float* enc_b2 = (const float*)d_in[7];
    const float* node_w1 = (const float*)d_in[8];
    const float* node_b1 = (const float*)d_in[9];
    const float* node_w2 = (const float*)d_in[10];
    const float* node_b2 = (const float*)d_in[11];
    const float* edge_w1 = (const float*)d_in[12];
    const float* edge_b1 = (const float*)d_in[13];
    const float* edge_w2 = (const float*)d_in[14];
    const float* edge_b2 = (const float*)d_in[15];
    const float* dec_w1 = (const float*)d_in[16];
    const float* dec_b1 = (const float*)d_in[17];
    const float* dec_w2 = (const float*)d_in[18];
    const float* dec_b2 = (const float*)d_in[19];
    const float* alpha  = (const float*)d_in[20];
    float* out = (float*)d_out;

    const int TB = 256;
    k_norm_part<<<1024, TB>>>(edges_init);     // zero aggs + block maxima
    k_norm_final<<<1, 1024>>>();

    int eb = (NE / 2 + TB - 1) / TB;
    int nb = (NN + TB - 1) / TB;

    k_enc<<<eb, TB>>>(edges_init, senders, receivers,
                      enc_w1, enc_b1, enc_w2, enc_b2);

    for (int r = 0; r < 3; r++) {
        if (r == 0)
            k_node<true><<<nb, TB>>>(nodes, node_w1, node_b1, node_w2, node_b2);
        else
            k_node<false><<<nb, TB>>>(nodes, node_w1, node_b1, node_w2, node_b2);

        if (r < 2)
            k_edge<false><<<eb, TB>>>(senders, receivers,
                                      edge_w1, edge_b1, edge_w2, edge_b2,
                                      dec_w1, dec_b1, dec_w2, dec_b2,
                                      edges_init, alpha, out);
        else
            k_edge<true><<<eb, TB>>>(senders, receivers,
                                     edge_w1, edge_b1, edge_w2, edge_b2,
                                     dec_w1, dec_b1, dec_w2, dec_b2,
                                     edges_init, alpha, out);
    }
}

// round 14
// speedup vs baseline: 1.0698x; 1.0698x over previous
#include <cuda_runtime.h>
#include <cuda_fp16.h>
#include <cuda_fp8.h>

#define NN 100000
#define NE 3200000
#define HID 16

typedef unsigned int u32;
typedef unsigned short u16;

// ---------------- scratch ----------------
__device__ uint4  g_e8[NE];           // 51.2 MB edge features (fp8 e4m3, 16B/edge)
__device__ __align__(32) __half g_agg_s[NN][HID];   // 3.2 MB f16 accumulators
__device__ __align__(32) __half g_agg_r[NN][HID];   // 3.2 MB
__device__ __half g_nodes_h[NN];      // 200 KB -- fits in one SM's L1D
__device__ float  g_part[1024];
__device__ float  g_norm;
__device__ float  g_inv_norm;

// ---------------- helpers ----------------
__device__ __forceinline__ u32 h2u(__half2 h) { return *(u32*)&h; }
__device__ __forceinline__ __half2 u2h(u32 v) { return *(__half2*)&v; }
__device__ __forceinline__ u32 packh2(float a, float b) {
    return h2u(__floats2half2_rn(a, b));
}
__device__ __forceinline__ float2 unpackh2(u32 v) {
    return __half22float2(u2h(v));
}
__device__ __forceinline__ float hsum2(__half2 a) {
    float2 f = __half22float2(a);
    return f.x + f.y;
}
__device__ __forceinline__ void red_add_v4h(void* p, u32 a, u32 b, u32 c, u32 d) {
    asm volatile("red.global.add.noftz.v4.f16x2 [%0], {%1, %2, %3, %4};"
                 :: "l"(p), "r"(a), "r"(b), "r"(c), "r"(d) : "memory");
}
__device__ __forceinline__ u16 pack8(float a, float b) {
    float2 f = make_float2(a, b);
    return (u16)__nv_cvt_float2_to_fp8x2(f, __NV_SATFINITE, __NV_E4M3);
}
__device__ __forceinline__ __half2 unp8(u16 v) {
    __half2_raw hr = __nv_cvt_fp8x2_to_halfraw2((__nv_fp8x2_storage_t)v, __NV_E4M3);
    return *(__half2*)&hr;
}

// 16->16 layer in f16x2 (weights as 2 uint4 of half2 k-pairs)
__device__ __forceinline__ __half2 dot16h(const uint4 wa, const uint4 wb,
                                          const __half2* x, __half2 acc) {
    acc = __hfma2(u2h(wa.x), x[0], acc);
    acc = __hfma2(u2h(wa.y), x[1], acc);
    acc = __hfma2(u2h(wa.z), x[2], acc);
    acc = __hfma2(u2h(wa.w), x[3], acc);
    acc = __hfma2(u2h(wb.x), x[4], acc);
    acc = __hfma2(u2h(wb.y), x[5], acc);
    acc = __hfma2(u2h(wb.z), x[6], acc);
    acc = __hfma2(u2h(wb.w), x[7], acc);
    return acc;
}

// ---------------- launch 0: zero aggs + per-block max |x| ----------------
__global__ __launch_bounds__(256) void k_norm_part(const float* __restrict__ x) {
    __shared__ float sm[8];
    int gid = blockIdx.x * blockDim.x + threadIdx.x;
    const int nf4 = NN * HID * 2 / 16;
    uint4 z = make_uint4(0u, 0u, 0u, 0u);
    if (gid < nf4) {
        ((uint4*)g_agg_s)[gid] = z;
        ((uint4*)g_agg_r)[gid] = z;
    }
    float m = 0.f;
    const float4* x4 = (const float4*)x;
    const int n4 = NE / 4;
    for (int i = gid; i < n4; i += gridDim.x * blockDim.x) {
        float4 v = x4[i];
        m = fmaxf(m, fmaxf(fmaxf(fabsf(v.x), fabsf(v.y)), fmaxf(fabsf(v.z), fabsf(v.w))));
    }
#pragma unroll
    for (int o = 16; o; o >>= 1) m = fmaxf(m, __shfl_xor_sync(0xffffffffu, m, o));
    if ((threadIdx.x & 31) == 0) sm[threadIdx.x >> 5] = m;
    __syncthreads();
    if (threadIdx.x < 8) {
        m = sm[threadIdx.x];
#pragma unroll
        for (int o = 4; o; o >>= 1) m = fmaxf(m, __shfl_xor_sync(0xffu, m, o));
        if (threadIdx.x == 0) g_part[blockIdx.x] = m;
    }
}

// ---------------- launch 1: finalize norm ----------------
__global__ __launch_bounds__(1024) void k_norm_final() {
    __shared__ float sm[32];
    float m = g_part[threadIdx.x];
#pragma unroll
    for (int o = 16; o; o >>= 1) m = fmaxf(m, __shfl_xor_sync(0xffffffffu, m, o));
    if ((threadIdx.x & 31) == 0) sm[threadIdx.x >> 5] = m;
    __syncthreads();
    if (threadIdx.x < 32) {
        m = sm[threadIdx.x];
#pragma unroll
        for (int o = 16; o; o >>= 1) m = fmaxf(m, __shfl_xor_sync(0xffffffffu, m, o));
        if (threadIdx.x == 0) { g_norm = m; g_inv_norm = 1.0f / m; }
    }
}

// ---------------- launch 2: encoder (2 edges/thread) ----------------
__global__ __launch_bounds__(256) void k_enc(
    const float* __restrict__ edges_init,
    const int* __restrict__ senders, const int* __restrict__ receivers,
    const float* __restrict__ w1g, const float* __restrict__ b1g,
    const float* __restrict__ w2g, const float* __restrict__ b2g)
{
    __shared__ __align__(16) float w1[HID], b1[HID];
    __shared__ __align__(16) u32 w2h[HID * 8];
    __shared__ __align__(16) u32 b2h[HID];
    int t = threadIdx.x;
    if (t < HID) {
        w1[t] = w1g[t]; b1[t] = b1g[t];
        b2h[t] = packh2(b2g[t], 0.f);
    }
    if (t < 128) {
        int j = t >> 3, kk = t & 7;
        w2h[j * 8 + kk] = packh2(w2g[j * HID + 2 * kk], w2g[j * HID + 2 * kk + 1]);
    }
    __syncthreads();

    int p = blockIdx.x * blockDim.x + t;
    if (p >= NE / 2) return;
    int i0 = 2 * p;

    float2 xi = ((const float2*)edges_init)[p];
    float inv = g_inv_norm;
    float x[2] = {xi.x * inv, xi.y * inv};
    int2 s2 = ((const int2*)senders)[p];
    int2 r2 = ((const int2*)receivers)[p];

    const uint4* w2v = (const uint4*)w2h;
    u32 uu[2][8];
    uint4 st[2];

#pragma unroll
    for (int ed = 0; ed < 2; ed++) {
        float h[HID];
#pragma unroll
        for (int j = 0; j < HID; j++) h[j] = fmaxf(fmaf(w1[j], x[ed], b1[j]), 0.f);
        __half2 hp[8];
#pragma unroll
        for (int q = 0; q < 8; q++) hp[q] = __floats2half2_rn(h[2 * q], h[2 * q + 1]);

        float e[HID];
#pragma unroll
        for (int j = 0; j < HID; j++) {
            __half2 acc = dot16h(w2v[j * 2], w2v[j * 2 + 1], hp, u2h(b2h[j]));
            e[j] = hsum2(acc);
        }
        u16 p8[8];
#pragma unroll
        for (int q = 0; q < 8; q++) {
            uu[ed][q] = packh2(e[2 * q], e[2 * q + 1]);
            p8[q] = pack8(e[2 * q], e[2 * q + 1]);
        }
        st[ed] = make_uint4((u32)p8[0] | ((u32)p8[1] << 16),
                            (u32)p8[2] | ((u32)p8[3] << 16),
                            (u32)p8[4] | ((u32)p8[5] << 16),
                            (u32)p8[6] | ((u32)p8[7] << 16));
    }
    g_e8[i0] = st[0];
    g_e8[i0 + 1] = st[1];

    char* ps0 = (char*)g_agg_s + (size_t)s2.x * 32;
    char* pr0 = (char*)g_agg_r + (size_t)r2.x * 32;
    char* ps1 = (char*)g_agg_s + (size_t)s2.y * 32;
    char* pr1 = (char*)g_agg_r + (size_t)r2.y * 32;
    red_add_v4h(ps0,      uu[0][0], uu[0][1], uu[0][2], uu[0][3]);
    red_add_v4h(ps1,      uu[1][0], uu[1][1], uu[1][2], uu[1][3]);
    red_add_v4h(pr0,      uu[0][0], uu[0][1], uu[0][2], uu[0][3]);
    red_add_v4h(pr1,      uu[1][0], uu[1][1], uu[1][2], uu[1][3]);
    red_add_v4h(ps0 + 16, uu[0][4], uu[0][5], uu[0][6], uu[0][7]);
    red_add_v4h(ps1 + 16, uu[1][4], uu[1][5], uu[1][6], uu[1][7]);
    red_add_v4h(pr0 + 16, uu[0][4], uu[0][5], uu[0][6], uu[0][7]);
    red_add_v4h(pr1 + 16, uu[1][4], uu[1][5], uu[1][6], uu[1][7]);
}

// ---------------- node update: fp32 math, f16 node store ----------------
template <bool FIRST>
__global__ __launch_bounds__(256) void k_node(
    const float* __restrict__ in_nodes,
    const float* __restrict__ w1g, const float* __restrict__ b1g,
    const float* __restrict__ w2g, const float* __restrict__ b2g)
{
    __shared__ __align__(16) float w1[HID * 36], b1[HID], w2[HID];
    __shared__ float b2s;
    int t = threadIdx.x;
    for (int i = t; i < HID * 33; i += blockDim.x) {
        int j = i / 33, c = i % 33;
        w1[j * 36 + c] = w1g[i];
    }
    if (t < HID) { b1[t] = b1g[t]; w2[t] = w2g[t]; }
    if (t == 0) b2s = b2g[0];
    __syncthreads();

    int n = blockIdx.x * blockDim.x + t;
    if (n >= NN) return;

    float xin[33];
    xin[0] = FIRST ? in_nodes[n] : __half2float(g_nodes_h[n]);
    uint4* as4 = (uint4*)g_agg_s[n];
    uint4* ar4 = (uint4*)g_agg_r[n];
#pragma unroll
    for (int half = 0; half < 2; half++) {
        uint4 a = as4[half];
        u32 w[4] = {a.x, a.y, a.z, a.w};
#pragma unroll
        for (int q = 0; q < 4; q++) {
            float2 f = unpackh2(w[q]);
            xin[1 + half * 8 + 2 * q] = f.x;
            xin[2 + half * 8 + 2 * q] = f.y;
        }
        uint4 b = ar4[half];
        u32 v[4] = {b.x, b.y, b.z, b.w};
#pragma unroll
        for (int q = 0; q < 4; q++) {
            float2 f = unpackh2(v[q]);
            xin[17 + half * 8 + 2 * q] = f.x;
            xin[18 + half * 8 + 2 * q] = f.y;
        }
    }
    uint4 z = make_uint4(0u, 0u, 0u, 0u);
    as4[0] = z; as4[1] = z; ar4[0] = z; ar4[1] = z;

    const float4* w1v = (const float4*)w1;
    float out = b2s;
#pragma unroll
    for (int j = 0; j < HID; j++) {
        float hj = b1[j];
#pragma unroll
        for (int q = 0; q < 8; q++) {
            float4 w = w1v[j * 9 + q];
            hj = fmaf(w.x, xin[4 * q], hj);
            hj = fmaf(w.y, xin[4 * q + 1], hj);
            hj = fmaf(w.z, xin[4 * q + 2], hj);
            hj = fmaf(w.w, xin[4 * q + 3], hj);
        }
        hj = fmaf(w1v[j * 9 + 8].x, xin[32], hj);
        out = fmaf(w2[j], fmaxf(hj, 0.f), out);
    }
    g_nodes_h[n] = __float2half_rn(out);
}

// ---------------- edge update: f16x2 MLPs, fp8 e, f16 node gathers ----------------
// LAST: decoder layer-1 fused into edge layer-2 (M = D1*W2, c = D1*eb2 + db1)
template <bool LAST>
__global__ __launch_bounds__(256) void k_edge(
    const int* __restrict__ senders, const int* __restrict__ receivers,
    const float* __restrict__ ew1g, const float* __restrict__ eb1g,
    const float* __restrict__ ew2g, const float* __restrict__ eb2g,
    const float* __restrict__ dw1g, const float* __restrict__ db1g,
    const float* __restrict__ dw2g, const float* __restrict__ db2g,
    const float* __restrict__ edges_init, const float* __restrict__ alpha_p,
    float* __restrict__ out)
{
    __shared__ __align__(16) u32 ew1h[HID * 8];
    __shared__ __align__(16) u32 ew1n[HID];
    __shared__ __align__(16) u32 eb1h[HID];
    __shared__ __align__(16) u32 ew2h[HID * 8];
    __shared__ __align__(16) u32 eb2h[HID];
    __shared__ __align__(16) float Mf[HID * HID];   // fp32 staging for fused M (LAST)
    __shared__ __align__(16) u32 Mh[HID * 8];       // fused M as f16x2 k-pairs
    __shared__ __align__(16) u32 ch[HID];           // fused bias {c, 0}
    __shared__ __align__(16) u32 dw2h[8];
    __shared__ float db2s, alphas;
    int t = threadIdx.x;
    if (t < 128) {
        int j = t >> 3, kk = t & 7;
        ew1h[j * 8 + kk] = packh2(ew1g[j * 18 + 2 * kk], ew1g[j * 18 + 2 * kk + 1]);
        ew2h[j * 8 + kk] = packh2(ew2g[j * HID + 2 * kk], ew2g[j * HID + 2 * kk + 1]);
    }
    if (t < HID) {
        ew1n[t] = packh2(ew1g[t * 18 + 16], ew1g[t * 18 + 17]);
        eb1h[t] = packh2(eb1g[t], 0.f);
        eb2h[t] = packh2(eb2g[t], 0.f);
    }
    if (LAST) {
        // M[j][k] = sum_m D1[j][m] * W2[m][k]   (256 entries, one per thread)
        {
            int j = t >> 4, k = t & 15;
            float acc = 0.f;
#pragma unroll
            for (int m = 0; m < HID; m++)
                acc += dw1g[j * HID + m] * ew2g[m * HID + k];
            Mf[t] = acc;
        }
        if (t >= 32 && t < 40) dw2h[t - 32] = packh2(dw2g[2 * (t - 32)], dw2g[2 * (t - 32) + 1]);
        if (t == 40) { db2s = db2g[0]; alphas = alpha_p[0]; }
        __syncthreads();
        if (t < 128) {
            int j = t >> 3, kp = t & 7;
            Mh[j * 8 + kp] = packh2(Mf[j * HID + 2 * kp], Mf[j * HID + 2 * kp + 1]);
        }
        if (t < HID) {
            // c[j] = db1[j] + sum_m D1[j][m] * eb2[m]
            float cc = db1g[t];
#pragma unroll
            for (int m = 0; m < HID; m++) cc += dw1g[t * HID + m] * eb2g[m];
            ch[t] = packh2(cc, 0.f);
        }
    }
    __syncthreads();

    int p = blockIdx.x * blockDim.x + t;
    if (p >= NE / 2) return;
    int i0 = 2 * p;

    int2 s2 = ((const int2*)senders)[p];
    int2 r2 = ((const int2*)receivers)[p];
    __half ns0 = g_nodes_h[s2.x], nr0 = g_nodes_h[r2.x];
    __half ns1 = g_nodes_h[s2.y], nr1 = g_nodes_h[r2.y];
    uint4 ev0 = g_e8[i0];
    uint4 ev1 = g_e8[i0 + 1];

    const uint4* w1v = (const uint4*)ew1h;
    const uint4* w2v = (const uint4*)ew2h;

    // layer 1 for both edges -> hp pairs
    __half2 hpa[2][8];
#pragma unroll
    for (int ed = 0; ed < 2; ed++) {
        uint4 ev = ed ? ev1 : ev0;
        __half2 epair[8];
        epair[0] = unp8((u16)(ev.x & 0xffffu)); epair[1] = unp8((u16)(ev.x >> 16));
        epair[2] = unp8((u16)(ev.y & 0xffffu)); epair[3] = unp8((u16)(ev.y >> 16));
        epair[4] = unp8((u16)(ev.z & 0xffffu)); epair[5] = unp8((u16)(ev.z >> 16));
        epair[6] = unp8((u16)(ev.w & 0xffffu)); epair[7] = unp8((u16)(ev.w >> 16));
        __half2 npair = ed ? __halves2half2(ns1, nr1) : __halves2half2(ns0, nr0);

        float h[HID];
#pragma unroll
        for (int j = 0; j < HID; j++) {
            __half2 acc = dot16h(w1v[j * 2], w1v[j * 2 + 1], epair, u2h(eb1h[j]));
            acc = __hfma2(u2h(ew1n[j]), npair, acc);
            h[j] = fmaxf(hsum2(acc), 0.f);
        }
#pragma unroll
        for (int q = 0; q < 8; q++) hpa[ed][q] = __floats2half2_rn(h[2 * q], h[2 * q + 1]);
    }

    if (!LAST) {
        u32 uu[2][8];
        uint4 st[2];
#pragma unroll
        for (int ed = 0; ed < 2; ed++) {
            float e2[HID];
#pragma unroll
            for (int j = 0; j < HID; j++) {
                __half2 acc = dot16h(w2v[j * 2], w2v[j * 2 + 1], hpa[ed], u2h(eb2h[j]));
                e2[j] = hsum2(acc);
            }
            u16 p8[8];
#pragma unroll
            for (int q = 0; q < 8; q++) {
                uu[ed][q] = packh2(e2[2 * q], e2[2 * q + 1]);
                p8[q] = pack8(e2[2 * q], e2[2 * q + 1]);
            }
            st[ed] = make_uint4((u32)p8[0] | ((u32)p8[1] << 16),
                                (u32)p8[2] | ((u32)p8[3] << 16),
                                (u32)p8[4] | ((u32)p8[5] << 16),
                                (u32)p8[6] | ((u32)p8[7] << 16));
        }
        g_e8[i0] = st[0];
        g_e8[i0 + 1] = st[1];

        char* ps0 = (char*)g_agg_s + (size_t)s2.x * 32;
        char* pr0 = (char*)g_agg_r + (size_t)r2.x * 32;
        char* ps1 = (char*)g_agg_s + (size_t)s2.y * 32;
        char* pr1 = (char*)g_agg_r + (size_t)r2.y * 32;
        red_add_v4h(ps0,      uu[0][0], uu[0][1], uu[0][2], uu[0][3]);
        red_add_v4h(ps1,      uu[1][0], uu[1][1], uu[1][2], uu[1][3]);
        red_add_v4h(pr0,      uu[0][0], uu[0][1], uu[0][2], uu[0][3]);
        red_add_v4h(pr1,      uu[1][0], uu[1][1], uu[1][2], uu[1][3]);
        red_add_v4h(ps0 + 16, uu[0][4], uu[0][5], uu[0][6], uu[0][7]);
        red_add_v4h(ps1 + 16, uu[1][4], uu[1][5], uu[1][6], uu[1][7]);
        red_add_v4h(pr0 + 16, uu[0][4], uu[0][5], uu[0][6], uu[0][7]);
        red_add_v4h(pr1 + 16, uu[1][4], uu[1][5], uu[1][6], uu[1][7]);
    } else {
        const uint4* Mv = (const uint4*)Mh;
        float2 ei = ((const float2*)edges_init)[p];
        float scale = alphas * g_norm;
        float oo[2];
#pragma unroll
        for (int ed = 0; ed < 2; ed++) {
            // h2 = relu(M*h + c) directly from hp (edge L2 + dec L1 fused)
            float h2[HID];
#pragma unroll
            for (int j = 0; j < HID; j++) {
                __half2 acc = dot16h(Mv[j * 2], Mv[j * 2 + 1], hpa[ed], u2h(ch[j]));
                h2[j] = fmaxf(hsum2(acc), 0.f);
            }
            __half2 h2p[8];
#pragma unroll
            for (int q = 0; q < 8; q++) h2p[q] = __floats2half2_rn(h2[2 * q], h2[2 * q + 1]);
            __half2 acc = __floats2half2_rn(0.f, 0.f);
#pragma unroll
            for (int q = 0; q < 8; q++) acc = __hfma2(u2h(dw2h[q]), h2p[q], acc);
            float sdec = db2s + hsum2(acc);
            oo[ed] = fmaf(scale, sdec, ed ? ei.y : ei.x);
        }
        ((float2*)out)[p] = make_float2(oo[0], oo[1]);
    }
}

// ---------------- launch ----------------
extern "C" void kernel_launch(void* const* d_in, const int* in_sizes, int n_in,
                              void* d_out, int out_size)
{
    const float* nodes      = (const float*)d_in[0];
    const float* edges_init = (const float*)d_in[1];
    const int*   senders    = (const int*)d_in[2];
    const int*   receivers  = (const int*)d_in[3];
    const float* enc_w1 = (const float*)d_in[4];
    const float* enc_b1 = (const float*)d_in[5];
    const float* enc_w2 = (const float*)d_in[6];
    const float* enc_b2 = (const float*)d_in[7];
    const float* node_w1 = (const float*)d_in[8];
    const float* node_b1 = (const float*)d_in[9];
    const float* node_w2 = (const float*)d_in[10];
    const float* node_b2 = (const float*)d_in[11];
    const float* edge_w1 = (const float*)d_in[12];
    const float* edge_b1 = (const float*)d_in[13];
    const float* edge_w2 = (const float*)d_in[14];
    const float* edge_b2 = (const float*)d_in[15];
    const float* dec_w1 = (const float*)d_in[16];
    const float* dec_b1 = (const float*)d_in[17];
    const float* dec_w2 = (const float*)d_in[18];
    const float* dec_b2 = (const float*)d_in[19];
    const float* alpha  = (const float*)d_in[20];
    float* out = (float*)d_out;

    const int TB = 256;
    k_norm_part<<<1024, TB>>>(edges_init);     // zero aggs + block maxima
    k_norm_final<<<1, 1024>>>();

    int eb = (NE / 2 + TB - 1) / TB;
    int nb = (NN + TB - 1) / TB;

    k_enc<<<eb, TB>>>(edges_init, senders, receivers,
                      enc_w1, enc_b1, enc_w2, enc_b2);

    for (int r = 0; r < 3; r++) {
        if (r == 0)
            k_node<true><<<nb, TB>>>(nodes, node_w1, node_b1, node_w2, node_b2);
        else
            k_node<false><<<nb, TB>>>(nodes, node_w1, node_b1, node_w2, node_b2);

        if (r < 2)
            k_edge<false><<<eb, TB>>>(senders, receivers,
                                      edge_w1, edge_b1, edge_w2, edge_b2,
                                      dec_w1, dec_b1, dec_w2, dec_b2,
                                      edges_init, alpha, out);
        else
            k_edge<true><<<eb, TB>>>(senders, receivers,
                                     edge_w1, edge_b1, edge_w2, edge_b2,
                                     dec_w1, dec_b1, dec_w2, dec_b2,
                                     edges_init, alpha, out);
    }
}